// round 12
// baseline (speedup 1.0000x reference)
#include <cuda_runtime.h>
#include <cstdint>

#define N_ 50000
#define K_ 32
#define D_ 128
#define EPS_ 1e-12f
#define WARPS_PER_BLOCK 8
#define THREADS_ (WARPS_PER_BLOCK * 32)
#define NBLOCKS_ ((N_ + WARPS_PER_BLOCK - 1) / WARPS_PER_BLOCK)   // 6250
#define ROWB_ 384   // packed row: 256B hi-plane + 128B lo-plane

__device__ uint8_t  g_pack[(size_t)N_ * ROWB_];   // 19.2 MB
__device__ double   g_block_partials[NBLOCKS_];
__device__ unsigned g_ticket = 0;                 // returns to 0 each run (graph-replay safe)

// ---- packed f32x2 helpers (Blackwell) ----
__device__ __forceinline__ uint64_t pk2(unsigned lo, unsigned hi) {
    uint64_t r; asm("mov.b64 %0, {%1, %2};" : "=l"(r) : "r"(lo), "r"(hi)); return r;
}
__device__ __forceinline__ uint64_t add2(uint64_t a, uint64_t b) {
    uint64_t r; asm("add.rn.f32x2 %0, %1, %2;" : "=l"(r) : "l"(a), "l"(b)); return r;
}
__device__ __forceinline__ uint64_t mul2(uint64_t a, uint64_t b) {
    uint64_t r; asm("mul.rn.f32x2 %0, %1, %2;" : "=l"(r) : "l"(a), "l"(b)); return r;
}
__device__ __forceinline__ uint64_t fma2(uint64_t a, uint64_t b, uint64_t c) {
    uint64_t r; asm("fma.rn.f32x2 %0, %1, %2, %3;" : "=l"(r) : "l"(a), "l"(b), "l"(c)); return r;
}
__device__ __forceinline__ float hsum2(uint64_t v) {
    unsigned x, y; asm("mov.b64 {%0, %1}, %2;" : "=r"(x), "=r"(y) : "l"(v));
    return __uint_as_float(x) + __uint_as_float(y);
}

// Warp-per-row prep: round fp32 to 24 bits and store [hi16 x128 | lo8 x128] packed row.
__global__ __launch_bounds__(THREADS_)
void snl_prep_kernel(const float* __restrict__ emb) {
    const int warp = threadIdx.x >> 5;
    const int lane = threadIdx.x & 31;
    const int i = blockIdx.x * WARPS_PER_BLOCK + warp;

    const uint4 y = reinterpret_cast<const uint4*>(emb + (size_t)i * D_)[lane];
    const unsigned r0 = y.x + 0x80u, r1 = y.y + 0x80u;
    const unsigned r2 = y.z + 0x80u, r3 = y.w + 0x80u;

    ushort4 h;
    h.x = (unsigned short)(r0 >> 16); h.y = (unsigned short)(r1 >> 16);
    h.z = (unsigned short)(r2 >> 16); h.w = (unsigned short)(r3 >> 16);
    uchar4 l;
    l.x = (unsigned char)(r0 >> 8); l.y = (unsigned char)(r1 >> 8);
    l.z = (unsigned char)(r2 >> 8); l.w = (unsigned char)(r3 >> 8);

    uint8_t* row = g_pack + (size_t)i * ROWB_;
    *reinterpret_cast<ushort4*>(row + 8 * lane) = h;            // hi plane [0,256)
    *reinterpret_cast<uchar4*>(row + 256 + 4 * lane) = l;       // lo plane [256,384)
}

__global__ __launch_bounds__(THREADS_, 7)
void snl_main_kernel(const float* __restrict__ emb,
                     const float* __restrict__ p,
                     const int* __restrict__ anchor,
                     float* __restrict__ out /* [0]=loss, [1..]=q */) {
    __shared__ double loss_s[WARPS_PER_BLOCK];
    __shared__ double red_s[THREADS_];
    __shared__ bool   is_last;

    const int warp = threadIdx.x >> 5;
    const int lane = threadIdx.x & 31;
    const int i = blockIdx.x * WARPS_PER_BLOCK + warp;   // 6250*8 == 50000 exactly
    float* __restrict__ out_q = out + 1;

    const int j_mine = anchor[(size_t)i * K_ + lane];    // lane k owns anchor k

    // yi exact; pre-negated and packed so (b - a) comes from one add2 each
    const float4 a0 = reinterpret_cast<const float4*>(emb + (size_t)i * D_)[lane];
    const uint64_t na01 = pk2(__float_as_uint(-a0.x), __float_as_uint(-a0.y));
    const uint64_t na23 = pk2(__float_as_uint(-a0.z), __float_as_uint(-a0.w));

    const bool hi16 = (lane & 16) != 0;
    const bool hi8  = (lane & 8) != 0;
    const bool hi4  = (lane & 4) != 0;

    // per-anchor partial of |a-b|^2: lane t covers dims 4t..4t+3
    auto partial = [&](int jr) -> float {
        const uint8_t* row = g_pack + (size_t)jr * ROWB_;
        const uint2    hw = *reinterpret_cast<const uint2*>(row + 8 * lane);
        const unsigned lw = *reinterpret_cast<const unsigned*>(row + 256 + 4 * lane);
        // fp32 bytes [b3 b2 b1 b0] = [hiB1, hiB0, lo8, junk]
        const unsigned bx = __byte_perm(hw.x, lw, 0x1044);
        const unsigned by = __byte_perm(hw.x, lw, 0x3255);
        const unsigned bz = __byte_perm(hw.y, lw, 0x1066);
        const unsigned bw = __byte_perm(hw.y, lw, 0x3277);
        const uint64_t d01 = add2(pk2(bx, by), na01);     // b - a
        const uint64_t d23 = add2(pk2(bz, bw), na23);
        return hsum2(fma2(d01, d01, mul2(d23, d23)));
    };

    auto fold = [&](float lo_v, float hi_v, bool up, int s) -> float {
        const float send = up ? lo_v : hi_v;
        return (up ? hi_v : lo_v) + __shfl_xor_sync(0xffffffffu, send, s);
    };

    // 8-way folded partials: w[g] covers anchors 8g..8g+7 (4 live registers).
    float w[K_ / 8];
    #pragma unroll
    for (int g = 0; g < K_ / 8; g++) {
        float u[4];
        #pragma unroll
        for (int h = 0; h < 4; h++) {
            const int jr0 = __shfl_sync(0xffffffffu, j_mine, 8 * g + 2 * h);
            const int jr1 = __shfl_sync(0xffffffffu, j_mine, 8 * g + 2 * h + 1);
            const float pa = partial(jr0);
            const float pb = partial(jr1);
            u[h] = fold(pa, pb, hi16, 16);          // idx bit0 = b16
        }
        const float v0 = fold(u[0], u[1], hi8, 8);  // idx bit1 = b8
        const float v1 = fold(u[2], u[3], hi8, 8);
        w[g] = fold(v0, v1, hi4, 4);                // idx bit2 = b4
    }

    // Recursive halving on 4 values: 3 shuffles; group g = lane&3.
    #pragma unroll
    for (int s = 2; s >= 1; s >>= 1) {
        const bool upper = (lane & s) != 0;
        #pragma unroll
        for (int k = 0; k < s; k++) {
            const float send = upper ? w[k] : w[k + s];
            const float recv = __shfl_xor_sync(0xffffffffu, send, s);
            w[k] = (upper ? w[k + s] : w[k]) + recv;
        }
    }
    // anchor owned by lane l:
    const int acol = 8 * (lane & 3) + 4 * ((lane >> 2) & 1)
                   + 2 * ((lane >> 3) & 1) + ((lane >> 4) & 1);

    // softmax over the 32 lanes of s = -d2
    const float sc = -w[0];
    float m = sc;
    #pragma unroll
    for (int o = 16; o; o >>= 1) m = fmaxf(m, __shfl_xor_sync(0xffffffffu, m, o));
    const float e = __expf(sc - m);
    float sum = e;
    #pragma unroll
    for (int o = 16; o; o >>= 1) sum += __shfl_xor_sync(0xffffffffu, sum, o);
    const float lse = m + __logf(sum);
    const float logq = sc - lse;
    const float q = __expf(logq);

    const float pv = p[(size_t)i * K_ + acol];
    out_q[(size_t)i * K_ + acol] = q;

    float contrib = pv * (__logf(pv + EPS_) - logq);
    #pragma unroll
    for (int o = 16; o; o >>= 1) contrib += __shfl_xor_sync(0xffffffffu, contrib, o);
    if (lane == 0) loss_s[warp] = (double)contrib;
    __syncthreads();

    if (threadIdx.x == 0) {
        double blk = 0.0;
        #pragma unroll
        for (int w2 = 0; w2 < WARPS_PER_BLOCK; w2++) blk += loss_s[w2];
        g_block_partials[blockIdx.x] = blk;
        __threadfence();
        unsigned t = atomicAdd(&g_ticket, 1u);
        is_last = (t == (unsigned)(NBLOCKS_ - 1));
    }
    __syncthreads();

    if (is_last) {
        __threadfence();
        double acc = 0.0;
        for (int b = threadIdx.x; b < NBLOCKS_; b += THREADS_)
            acc += g_block_partials[b];
        red_s[threadIdx.x] = acc;
        __syncthreads();
        #pragma unroll
        for (int o = THREADS_ / 2; o; o >>= 1) {
            if (threadIdx.x < o) red_s[threadIdx.x] += red_s[threadIdx.x + o];
            __syncthreads();
        }
        if (threadIdx.x == 0) {
            out[0] = (float)(red_s[0] / (double)N_);
            g_ticket = 0;
        }
    }
}

extern "C" void kernel_launch(void* const* d_in, const int* in_sizes, int n_in,
                              void* d_out, int out_size) {
    const float* emb    = (const float*)d_in[0];  // output_embedding [N, D] f32
    const float* p      = (const float*)d_in[1];  // input_similarity [N, K] f32
    const int*   anchor = (const int*)d_in[2];    // anchor_idx [N, K] int32
    float* out = (float*)d_out;                   // [0]=loss, [1..]=q row-major

    snl_prep_kernel<<<NBLOCKS_, THREADS_>>>(emb);
    snl_main_kernel<<<NBLOCKS_, THREADS_>>>(emb, p, anchor, out);
}

// round 13
// speedup vs baseline: 1.0539x; 1.0539x over previous
#include <cuda_runtime.h>
#include <cstdint>

#define N_ 50000
#define K_ 32
#define D_ 128
#define EPS_ 1e-12f
#define WARPS_PER_BLOCK 8
#define THREADS_ (WARPS_PER_BLOCK * 32)
#define NBLOCKS_ ((N_ + WARPS_PER_BLOCK - 1) / WARPS_PER_BLOCK)   // 6250
#define ROWB_ 384   // packed row: 256B hi-plane + 128B lo-plane

__device__ uint8_t  g_pack[(size_t)N_ * ROWB_];   // 19.2 MB
__device__ double   g_block_partials[NBLOCKS_];
__device__ unsigned g_ticket = 0;                 // returns to 0 each run (graph-replay safe)

// Warp-per-row prep: round fp32 to 24 bits, store [hi16 x128 | lo8 x128] packed row.
__global__ __launch_bounds__(THREADS_)
void snl_prep_kernel(const float* __restrict__ emb) {
    const int warp = threadIdx.x >> 5;
    const int lane = threadIdx.x & 31;
    const int i = blockIdx.x * WARPS_PER_BLOCK + warp;

    const uint4 y = reinterpret_cast<const uint4*>(emb + (size_t)i * D_)[lane];
    const unsigned r0 = y.x + 0x80u, r1 = y.y + 0x80u;
    const unsigned r2 = y.z + 0x80u, r3 = y.w + 0x80u;

    ushort4 h;
    h.x = (unsigned short)(r0 >> 16); h.y = (unsigned short)(r1 >> 16);
    h.z = (unsigned short)(r2 >> 16); h.w = (unsigned short)(r3 >> 16);
    uchar4 l;
    l.x = (unsigned char)(r0 >> 8); l.y = (unsigned char)(r1 >> 8);
    l.z = (unsigned char)(r2 >> 8); l.w = (unsigned char)(r3 >> 8);

    uint8_t* row = g_pack + (size_t)i * ROWB_;
    *reinterpret_cast<ushort4*>(row + 8 * lane) = h;        // hi plane [0,256)
    *reinterpret_cast<uchar4*>(row + 256 + 4 * lane) = l;   // lo plane [256,384)
}

__global__ __launch_bounds__(THREADS_, 5)
void snl_main_kernel(const float* __restrict__ emb,
                     const float* __restrict__ p,
                     const int* __restrict__ anchor,
                     float* __restrict__ out /* [0]=loss, [1..]=q */) {
    __shared__ double loss_s[WARPS_PER_BLOCK];
    __shared__ double red_s[THREADS_];
    __shared__ bool   is_last;

    const int warp = threadIdx.x >> 5;
    const int lane = threadIdx.x & 31;
    const int i = blockIdx.x * WARPS_PER_BLOCK + warp;   // 6250*8 == 50000 exactly
    float* __restrict__ out_q = out + 1;

    const int j_mine = anchor[(size_t)i * K_ + lane];    // lane k owns anchor k

    // yi exact: lane t holds dims [4t, 4t+4)
    const float4 a = reinterpret_cast<const float4*>(emb + (size_t)i * D_)[lane];

    const bool hi16 = (lane & 16) != 0;
    const bool hi8  = (lane & 8) != 0;
    const bool hi4  = (lane & 4) != 0;

    auto fold = [&](float lo_v, float hi_v, bool up, int s) -> float {
        const float send = up ? lo_v : hi_v;
        return (up ? hi_v : lo_v) + __shfl_xor_sync(0xffffffffu, send, s);
    };

    // 8-way folded partials: w[g] covers anchors 8g..8g+7.
    // Each group: batch ALL 16 loads first (MLP~16), then decode+fold.
    float w[K_ / 8];
    #pragma unroll
    for (int g = 0; g < K_ / 8; g++) {
        // broadcast the 8 anchor indices for this group
        uint2    hw[8];
        unsigned lw[8];
        #pragma unroll
        for (int h = 0; h < 8; h++) {
            const int jr = __shfl_sync(0xffffffffu, j_mine, 8 * g + h);
            const uint8_t* row = g_pack + (size_t)jr * ROWB_;
            hw[h] = *reinterpret_cast<const uint2*>(row + 8 * lane);
            lw[h] = *reinterpret_cast<const unsigned*>(row + 256 + 4 * lane);
        }

        float pp[8];
        #pragma unroll
        for (int h = 0; h < 8; h++) {
            // fp32 bytes [b3 b2 b1 b0] = [hiB1, hiB0, lo8, junk]
            const float bx = __uint_as_float(__byte_perm(hw[h].x, lw[h], 0x1044));
            const float by = __uint_as_float(__byte_perm(hw[h].x, lw[h], 0x3255));
            const float bz = __uint_as_float(__byte_perm(hw[h].y, lw[h], 0x1066));
            const float bw = __uint_as_float(__byte_perm(hw[h].y, lw[h], 0x3277));
            const float dx = a.x - bx, dy = a.y - by, dz = a.z - bz, dw = a.w - bw;
            float pr = dx * dx;
            pr = fmaf(dy, dy, pr);
            pr = fmaf(dz, dz, pr);
            pr = fmaf(dw, dw, pr);
            pp[h] = pr;
        }

        float u[4];
        #pragma unroll
        for (int h = 0; h < 4; h++)
            u[h] = fold(pp[2 * h], pp[2 * h + 1], hi16, 16);   // idx bit0 = b16
        const float v0 = fold(u[0], u[1], hi8, 8);             // idx bit1 = b8
        const float v1 = fold(u[2], u[3], hi8, 8);
        w[g] = fold(v0, v1, hi4, 4);                           // idx bit2 = b4
    }

    // Recursive halving on 4 values: 3 shuffles; group g = lane&3.
    #pragma unroll
    for (int s = 2; s >= 1; s >>= 1) {
        const bool upper = (lane & s) != 0;
        #pragma unroll
        for (int k = 0; k < s; k++) {
            const float send = upper ? w[k] : w[k + s];
            const float recv = __shfl_xor_sync(0xffffffffu, send, s);
            w[k] = (upper ? w[k + s] : w[k]) + recv;
        }
    }
    // anchor owned by lane l:
    const int acol = 8 * (lane & 3) + 4 * ((lane >> 2) & 1)
                   + 2 * ((lane >> 3) & 1) + ((lane >> 4) & 1);

    // softmax over the 32 lanes of s = -d2
    const float sc = -w[0];
    float m = sc;
    #pragma unroll
    for (int o = 16; o; o >>= 1) m = fmaxf(m, __shfl_xor_sync(0xffffffffu, m, o));
    const float e = __expf(sc - m);
    float sum = e;
    #pragma unroll
    for (int o = 16; o; o >>= 1) sum += __shfl_xor_sync(0xffffffffu, sum, o);
    const float lse = m + __logf(sum);
    const float logq = sc - lse;
    const float q = __expf(logq);

    const float pv = p[(size_t)i * K_ + acol];
    out_q[(size_t)i * K_ + acol] = q;

    float contrib = pv * (__logf(pv + EPS_) - logq);
    #pragma unroll
    for (int o = 16; o; o >>= 1) contrib += __shfl_xor_sync(0xffffffffu, contrib, o);
    if (lane == 0) loss_s[warp] = (double)contrib;
    __syncthreads();

    if (threadIdx.x == 0) {
        double blk = 0.0;
        #pragma unroll
        for (int w2 = 0; w2 < WARPS_PER_BLOCK; w2++) blk += loss_s[w2];
        g_block_partials[blockIdx.x] = blk;
        __threadfence();
        unsigned t = atomicAdd(&g_ticket, 1u);
        is_last = (t == (unsigned)(NBLOCKS_ - 1));
    }
    __syncthreads();

    if (is_last) {
        __threadfence();
        double acc = 0.0;
        for (int b = threadIdx.x; b < NBLOCKS_; b += THREADS_)
            acc += g_block_partials[b];
        red_s[threadIdx.x] = acc;
        __syncthreads();
        #pragma unroll
        for (int o = THREADS_ / 2; o; o >>= 1) {
            if (threadIdx.x < o) red_s[threadIdx.x] += red_s[threadIdx.x + o];
            __syncthreads();
        }
        if (threadIdx.x == 0) {
            out[0] = (float)(red_s[0] / (double)N_);
            g_ticket = 0;
        }
    }
}

extern "C" void kernel_launch(void* const* d_in, const int* in_sizes, int n_in,
                              void* d_out, int out_size) {
    const float* emb    = (const float*)d_in[0];  // output_embedding [N, D] f32
    const float* p      = (const float*)d_in[1];  // input_similarity [N, K] f32
    const int*   anchor = (const int*)d_in[2];    // anchor_idx [N, K] int32
    float* out = (float*)d_out;                   // [0]=loss, [1..]=q row-major

    snl_prep_kernel<<<NBLOCKS_, THREADS_>>>(emb);
    snl_main_kernel<<<NBLOCKS_, THREADS_>>>(emb, p, anchor, out);
}